// round 5
// baseline (speedup 1.0000x reference)
#include <cuda_runtime.h>
#include <cuda_bf16.h>

// Problem constants (fixed shapes)
#define Nn 5570          // nodes
#define NP 5584          // padded to multiple of 16 (349*16)
#define Jj 576           // padded column count: 16*35=560 real + Z col (560) + pad
#define Bb 16
#define Cc 35

// Scratch (device globals — no allocation allowed). Zero-initialized at load;
// pad rows [Nn, NP) of g_V / g_E are never written -> stay 0 (deterministic).
__device__ float g_V[NP * Jj];    // V[m][j], j = b*35+c (j<560), j==560 -> 1, else 0
__device__ float g_X1[Nn * Jj];   // unnormalized S@V; col 560 = Z_n
__device__ float g_E[NP * 4];     // padded copy of e

// ---------------------------------------------------------------------------
// Kernel 1: build V (transpose x into [N, 576]) and padded e copy.
// ---------------------------------------------------------------------------
__global__ void prep_kernel(const float* __restrict__ x,
                            const float* __restrict__ e) {
    int idx = blockIdx.x * blockDim.x + threadIdx.x;
    if (idx < Nn * 4) g_E[idx] = e[idx];
    if (idx < Nn * Jj) {
        int m = idx / Jj;
        int j = idx - m * Jj;
        float v;
        if (j < Bb * Cc) {
            int b = j / Cc;
            int c = j - b * Cc;
            v = x[(b * Nn + m) * Cc + c];
        } else {
            v = (j == Bb * Cc) ? 1.0f : 0.0f;  // Z column
        }
        g_V[m * Jj + j] = v;
    }
}

// ---------------------------------------------------------------------------
// Kernel 2: xg1 = S @ V with S[n,m] = exp(relu(e_n . e_m)) generated on the fly.
// Block tile: BM=32 n-rows x BN=288 j-cols, BK=16. 192 threads, thread tile 4x12.
// ---------------------------------------------------------------------------
__global__ __launch_bounds__(192, 3) void gemm_kernel() {
    __shared__ float sEn[32][4];
    __shared__ float sEm[16][4];
    __shared__ float sS[16][32];     // scores transposed [m][n]
    __shared__ float sV[16][288];

    const int tid = threadIdx.x;
    const int jt = tid % 24;         // 24 j-threads * 12 cols = 288
    const int nt = tid / 24;         // 8 n-threads * 4 rows = 32
    const int n0 = blockIdx.x * 32;
    const int j0 = blockIdx.y * 288;

    if (tid < 128) {
        int nn = tid >> 2, d = tid & 3;
        int n = n0 + nn;
        if (n >= Nn) n = Nn - 1;     // clamped rows discarded at store
        sEn[nn][d] = g_E[n * 4 + d];
    }

    float acc[4][12];
#pragma unroll
    for (int i = 0; i < 4; ++i)
#pragma unroll
        for (int j = 0; j < 12; ++j) acc[i][j] = 0.0f;

    for (int mt = 0; mt < NP / 16; ++mt) {
        // load V tile: 16x288 floats = 1152 float4, 6 per thread
        const float4* Vg = (const float4*)(g_V + (size_t)mt * 16 * Jj + j0);
#pragma unroll
        for (int r = 0; r < 6; ++r) {
            int t = tid + r * 192;
            int mm = t / 72;
            int q = t - mm * 72;
            ((float4*)sV[mm])[q] = Vg[mm * (Jj / 4) + q];
        }
        if (tid < 64) {
            int mm = tid >> 2, d = tid & 3;
            sEm[mm][d] = g_E[(mt * 16 + mm) * 4 + d];
        }
        __syncthreads();

        // scores: 16*32 = 512
        for (int t = tid; t < 512; t += 192) {
            int mm = t >> 5, nn = t & 31;
            float dot = sEn[nn][0] * sEm[mm][0] + sEn[nn][1] * sEm[mm][1] +
                        sEn[nn][2] * sEm[mm][2] + sEn[nn][3] * sEm[mm][3];
            sS[mm][nn] = __expf(fmaxf(dot, 0.0f));
        }
        __syncthreads();

#pragma unroll
        for (int mm = 0; mm < 16; ++mm) {
            float4 s4 = *(const float4*)&sS[mm][nt * 4];
            const float* vp = &sV[mm][jt * 12];
            float4 v0 = *(const float4*)(vp);
            float4 v1 = *(const float4*)(vp + 4);
            float4 v2 = *(const float4*)(vp + 8);
            float sa[4] = {s4.x, s4.y, s4.z, s4.w};
            float va[12] = {v0.x, v0.y, v0.z, v0.w,
                            v1.x, v1.y, v1.z, v1.w,
                            v2.x, v2.y, v2.z, v2.w};
#pragma unroll
            for (int i = 0; i < 4; ++i)
#pragma unroll
                for (int j = 0; j < 12; ++j)
                    acc[i][j] += sa[i] * va[j];
        }
        __syncthreads();
    }

#pragma unroll
    for (int i = 0; i < 4; ++i) {
        int n = n0 + nt * 4 + i;
        if (n < Nn) {
            float4* o = (float4*)(g_X1 + (size_t)n * Jj + j0 + jt * 12);
            o[0] = make_float4(acc[i][0], acc[i][1], acc[i][2], acc[i][3]);
            o[1] = make_float4(acc[i][4], acc[i][5], acc[i][6], acc[i][7]);
            o[2] = make_float4(acc[i][8], acc[i][9], acc[i][10], acc[i][11]);
        }
    }
}

// ---------------------------------------------------------------------------
// Kernel 3: per-node epilogue. H=0 => Z is dead; only R and C needed.
// out[b,n] = relu((1-R)*C) . lin_w + lin_b
// ---------------------------------------------------------------------------
__global__ void epi_kernel(const float* __restrict__ x,
                           const float* __restrict__ e,
                           const float* __restrict__ w_gate,
                           const float* __restrict__ b_gate,
                           const float* __restrict__ w_update,
                           const float* __restrict__ b_update,
                           const float* __restrict__ lin_w,
                           const float* __restrict__ lin_b,
                           float* __restrict__ out) {
    const int n = blockIdx.x;
    const int tid = threadIdx.x;  // 64 threads

    __shared__ float se[4];
    __shared__ float sWg[2][35][4];
    __shared__ float sbg[4];
    __shared__ float sWu[2][35][2];
    __shared__ float sbu[2];
    __shared__ float sxs[16][36];
    __shared__ float sxg[16][36];
    __shared__ float sy[16][2];

    if (tid < 4) se[tid] = e[n * 4 + tid];
    __syncthreads();

    // W_gate[n,k,i,o] = sum_d e[n,d] * w_gate[d,k,i,o]  (only i<35 needed)
    for (int t = tid; t < 280; t += 64) {
        int o = t & 3;
        int t2 = t >> 2;
        int i = t2 % 35;
        int k = t2 / 35;
        float s = 0.0f;
#pragma unroll
        for (int d = 0; d < 4; ++d)
            s += se[d] * w_gate[(((d * 2) + k) * 37 + i) * 4 + o];
        sWg[k][i][o] = s;
    }
    if (tid < 4) {
        float s = 0.0f;
#pragma unroll
        for (int d = 0; d < 4; ++d) s += se[d] * b_gate[d * 4 + tid];
        sbg[tid] = s;
    }
    for (int t = tid; t < 140; t += 64) {
        int o = t & 1;
        int t2 = t >> 1;
        int i = t2 % 35;
        int k = t2 / 35;
        float s = 0.0f;
#pragma unroll
        for (int d = 0; d < 4; ++d)
            s += se[d] * w_update[(((d * 2) + k) * 37 + i) * 2 + o];
        sWu[k][i][o] = s;
    }
    if (tid < 2) {
        float s = 0.0f;
#pragma unroll
        for (int d = 0; d < 4; ++d) s += se[d] * b_update[d * 2 + tid];
        sbu[tid] = s;
    }

    const float invZ = 1.0f / g_X1[(size_t)n * Jj + 560];
    for (int t = tid; t < 560; t += 64) {
        int b = t / 35;
        int c = t - b * 35;
        sxs[b][c] = x[(b * Nn + n) * 35 + c];
        sxg[b][c] = g_X1[(size_t)n * Jj + t] * invZ;
    }
    __syncthreads();

    if (tid < 32) {
        int b = tid >> 1, o = tid & 1;
        float gr = sbg[o + 2];   // R gate (o+2)
        float cu = sbu[o];       // candidate C
#pragma unroll
        for (int i = 0; i < 35; ++i) {
            float xs = sxs[b][i];
            float xg = sxg[b][i];
            gr += xs * sWg[0][i][o + 2] + xg * sWg[1][i][o + 2];
            cu += xs * sWu[0][i][o] + xg * sWu[1][i][o];
        }
        float R = 1.0f / (1.0f + __expf(-gr));
        float Cv = tanhf(cu);
        float h = (1.0f - R) * Cv;
        sy[b][o] = fmaxf(h, 0.0f) * lin_w[o];
    }
    __syncthreads();

    if (tid < 16) {
        out[tid * Nn + n] = sy[tid][0] + sy[tid][1] + lin_b[0];
    }
}

extern "C" void kernel_launch(void* const* d_in, const int* in_sizes, int n_in,
                              void* d_out, int out_size) {
    const float* x        = (const float*)d_in[0];
    const float* e        = (const float*)d_in[1];
    const float* w_gate   = (const float*)d_in[2];
    const float* b_gate   = (const float*)d_in[3];
    const float* w_update = (const float*)d_in[4];
    const float* b_update = (const float*)d_in[5];
    const float* lin_w    = (const float*)d_in[6];
    const float* lin_b    = (const float*)d_in[7];
    float* out = (float*)d_out;

    int total = Nn * Jj;
    prep_kernel<<<(total + 255) / 256, 256>>>(x, e);

    dim3 g2((Nn + 31) / 32, 2);  // 175 x 2
    gemm_kernel<<<g2, 192>>>();

    epi_kernel<<<Nn, 64>>>(x, e, w_gate, b_gate, w_update, b_update,
                           lin_w, lin_b, out);
}

// round 6
// speedup vs baseline: 1.0817x; 1.0817x over previous
#include <cuda_runtime.h>
#include <cuda_bf16.h>

// Problem constants (fixed shapes)
#define Nn 5570          // nodes
#define NP 5584          // padded to multiple of 16 (349*16)
#define Jj 576           // padded column count: 16*35=560 real + Z col (560) + pad
#define Bb 16
#define Cc 35

// Scratch (device globals — no allocation allowed). Zero-initialized at load;
// pad rows [Nn, NP) of g_V / g_E are never written -> stay 0 (deterministic).
__device__ float g_V[NP * Jj];    // V[m][j], j = b*35+c (j<560), j==560 -> 1, else 0
__device__ float g_X1[Nn * Jj];   // unnormalized S@V; col 560 = Z_n
__device__ float g_E[NP * 4];     // padded copy of e

// ---------------------------------------------------------------------------
// Packed fp32x2 helpers (Blackwell dual-FP32 path; only reachable via PTX)
// ---------------------------------------------------------------------------
__device__ __forceinline__ unsigned long long pack2(float a) {
    unsigned long long r;
    asm("mov.b64 %0, {%1, %1};" : "=l"(r) : "f"(a));
    return r;
}
__device__ __forceinline__ void ffma2(unsigned long long& d,
                                      unsigned long long a,
                                      unsigned long long b) {
    asm("fma.rn.f32x2 %0, %1, %2, %3;" : "=l"(d) : "l"(a), "l"(b), "l"(d));
}
__device__ __forceinline__ void unpack2(unsigned long long v, float& lo, float& hi) {
    asm("mov.b64 {%0, %1}, %2;" : "=f"(lo), "=f"(hi) : "l"(v));
}

// ---------------------------------------------------------------------------
// Kernel 1: build V (transpose x into [N, 576]) and padded e copy.
// ---------------------------------------------------------------------------
__global__ void prep_kernel(const float* __restrict__ x,
                            const float* __restrict__ e) {
    int idx = blockIdx.x * blockDim.x + threadIdx.x;
    if (idx < Nn * 4) g_E[idx] = e[idx];
    if (idx < Nn * Jj) {
        int m = idx / Jj;
        int j = idx - m * Jj;
        float v;
        if (j < Bb * Cc) {
            int b = j / Cc;
            int c = j - b * Cc;
            v = x[(b * Nn + m) * Cc + c];
        } else {
            v = (j == Bb * Cc) ? 1.0f : 0.0f;  // Z column
        }
        g_V[m * Jj + j] = v;
    }
}

// ---------------------------------------------------------------------------
// Kernel 2: xg1 = S @ V, S[n,m] = exp(relu(e_n . e_m)) generated on the fly.
// Block tile: BM=32 n-rows x BN=288 j-cols, BK=16. 96 threads, thread tile
// 8x12, accumulators packed as fp32x2 pairs over j (FFMA2 inner loop).
// Per thread-mm: 80 B LDS for 96 FMA (0.83 B/FMA) -> crossbar 107 B/cyc < 128.
// ---------------------------------------------------------------------------
__global__ __launch_bounds__(96, 4) void gemm_kernel() {
    __shared__ float sEn[32][4];
    __shared__ float sEm[16][4];
    __shared__ __align__(16) float sS[16][32];     // scores transposed [m][n]
    __shared__ __align__(16) float sV[16][288];

    const int tid = threadIdx.x;
    const int jt = tid % 24;         // 24 j-threads * 12 cols = 288
    const int nt = tid / 24;         // 4 n-threads * 8 rows = 32
    const int n0 = blockIdx.x * 32;
    const int j0 = blockIdx.y * 288;

    for (int t = tid; t < 128; t += 96) {
        int nn = t >> 2, d = t & 3;
        int n = n0 + nn;
        if (n >= Nn) n = Nn - 1;     // clamped rows discarded at store
        sEn[nn][d] = g_E[n * 4 + d];
    }

    unsigned long long acc[8][6];    // 8 rows x 6 j-pairs (12 cols)
#pragma unroll
    for (int i = 0; i < 8; ++i)
#pragma unroll
        for (int j = 0; j < 6; ++j) acc[i][j] = 0ull;   // bits(0,0) == (0.f,0.f)

    for (int mt = 0; mt < NP / 16; ++mt) {
        // load V tile: 16x288 floats = 1152 float4, 12 per thread
        const float4* Vg = (const float4*)(g_V + (size_t)mt * 16 * Jj + j0);
#pragma unroll
        for (int r = 0; r < 12; ++r) {
            int t = tid + r * 96;
            int mm = t / 72;
            int q = t - mm * 72;
            ((float4*)sV[mm])[q] = Vg[mm * (Jj / 4) + q];
        }
        if (tid < 64) {
            int mm = tid >> 2, d = tid & 3;
            sEm[mm][d] = g_E[(mt * 16 + mm) * 4 + d];
        }
        __syncthreads();

        // scores: 16*32 = 512
        for (int t = tid; t < 512; t += 96) {
            int mm = t >> 5, nn = t & 31;
            float dot = sEn[nn][0] * sEm[mm][0] + sEn[nn][1] * sEm[mm][1] +
                        sEn[nn][2] * sEm[mm][2] + sEn[nn][3] * sEm[mm][3];
            sS[mm][nn] = __expf(fmaxf(dot, 0.0f));
        }
        __syncthreads();

#pragma unroll
        for (int mm = 0; mm < 16; ++mm) {
            // 8 score scalars for this thread's rows -> broadcast pairs
            float4 sa = *(const float4*)&sS[mm][nt * 8];
            float4 sb = *(const float4*)&sS[mm][nt * 8 + 4];
            unsigned long long s2[8];
            s2[0] = pack2(sa.x); s2[1] = pack2(sa.y);
            s2[2] = pack2(sa.z); s2[3] = pack2(sa.w);
            s2[4] = pack2(sb.x); s2[5] = pack2(sb.y);
            s2[6] = pack2(sb.z); s2[7] = pack2(sb.w);
            // 12 V values = 6 packed pairs, loaded directly
            const ulonglong2* vp = (const ulonglong2*)&sV[mm][jt * 12];
            ulonglong2 va = vp[0], vb = vp[1], vc = vp[2];
            unsigned long long v2[6] = {va.x, va.y, vb.x, vb.y, vc.x, vc.y};
#pragma unroll
            for (int i = 0; i < 8; ++i)
#pragma unroll
                for (int j = 0; j < 6; ++j)
                    ffma2(acc[i][j], s2[i], v2[j]);
        }
        __syncthreads();
    }

#pragma unroll
    for (int i = 0; i < 8; ++i) {
        int n = n0 + nt * 8 + i;
        if (n < Nn) {
            float r[12];
#pragma unroll
            for (int j = 0; j < 6; ++j) unpack2(acc[i][j], r[2 * j], r[2 * j + 1]);
            float4* o = (float4*)(g_X1 + (size_t)n * Jj + j0 + jt * 12);
            o[0] = make_float4(r[0], r[1], r[2], r[3]);
            o[1] = make_float4(r[4], r[5], r[6], r[7]);
            o[2] = make_float4(r[8], r[9], r[10], r[11]);
        }
    }
}

// ---------------------------------------------------------------------------
// Kernel 3: per-node epilogue. H=0 => Z is dead; only R and C needed.
// out[b,n] = relu((1-R)*C) . lin_w + lin_b
// ---------------------------------------------------------------------------
__global__ void epi_kernel(const float* __restrict__ x,
                           const float* __restrict__ e,
                           const float* __restrict__ w_gate,
                           const float* __restrict__ b_gate,
                           const float* __restrict__ w_update,
                           const float* __restrict__ b_update,
                           const float* __restrict__ lin_w,
                           const float* __restrict__ lin_b,
                           float* __restrict__ out) {
    const int n = blockIdx.x;
    const int tid = threadIdx.x;  // 64 threads

    __shared__ float se[4];
    __shared__ float sWg[2][35][4];
    __shared__ float sbg[4];
    __shared__ float sWu[2][35][2];
    __shared__ float sbu[2];
    __shared__ float sxs[16][36];
    __shared__ float sxg[16][36];
    __shared__ float sy[16][2];

    if (tid < 4) se[tid] = e[n * 4 + tid];
    __syncthreads();

    for (int t = tid; t < 280; t += 64) {
        int o = t & 3;
        int t2 = t >> 2;
        int i = t2 % 35;
        int k = t2 / 35;
        float s = 0.0f;
#pragma unroll
        for (int d = 0; d < 4; ++d)
            s += se[d] * w_gate[(((d * 2) + k) * 37 + i) * 4 + o];
        sWg[k][i][o] = s;
    }
    if (tid < 4) {
        float s = 0.0f;
#pragma unroll
        for (int d = 0; d < 4; ++d) s += se[d] * b_gate[d * 4 + tid];
        sbg[tid] = s;
    }
    for (int t = tid; t < 140; t += 64) {
        int o = t & 1;
        int t2 = t >> 1;
        int i = t2 % 35;
        int k = t2 / 35;
        float s = 0.0f;
#pragma unroll
        for (int d = 0; d < 4; ++d)
            s += se[d] * w_update[(((d * 2) + k) * 37 + i) * 2 + o];
        sWu[k][i][o] = s;
    }
    if (tid < 2) {
        float s = 0.0f;
#pragma unroll
        for (int d = 0; d < 4; ++d) s += se[d] * b_update[d * 2 + tid];
        sbu[tid] = s;
    }

    const float invZ = 1.0f / g_X1[(size_t)n * Jj + 560];
    for (int t = tid; t < 560; t += 64) {
        int b = t / 35;
        int c = t - b * 35;
        sxs[b][c] = x[(b * Nn + n) * 35 + c];
        sxg[b][c] = g_X1[(size_t)n * Jj + t] * invZ;
    }
    __syncthreads();

    if (tid < 32) {
        int b = tid >> 1, o = tid & 1;
        float gr = sbg[o + 2];   // R gate (o+2)
        float cu = sbu[o];       // candidate C
#pragma unroll
        for (int i = 0; i < 35; ++i) {
            float xs = sxs[b][i];
            float xg = sxg[b][i];
            gr += xs * sWg[0][i][o + 2] + xg * sWg[1][i][o + 2];
            cu += xs * sWu[0][i][o] + xg * sWu[1][i][o];
        }
        float R = 1.0f / (1.0f + __expf(-gr));
        float Cv = tanhf(cu);
        float h = (1.0f - R) * Cv;
        sy[b][o] = fmaxf(h, 0.0f) * lin_w[o];
    }
    __syncthreads();

    if (tid < 16) {
        out[tid * Nn + n] = sy[tid][0] + sy[tid][1] + lin_b[0];
    }
}

extern "C" void kernel_launch(void* const* d_in, const int* in_sizes, int n_in,
                              void* d_out, int out_size) {
    const float* x        = (const float*)d_in[0];
    const float* e        = (const float*)d_in[1];
    const float* w_gate   = (const float*)d_in[2];
    const float* b_gate   = (const float*)d_in[3];
    const float* w_update = (const float*)d_in[4];
    const float* b_update = (const float*)d_in[5];
    const float* lin_w    = (const float*)d_in[6];
    const float* lin_b    = (const float*)d_in[7];
    float* out = (float*)d_out;

    int total = Nn * Jj;
    prep_kernel<<<(total + 255) / 256, 256>>>(x, e);

    dim3 g2((Nn + 31) / 32, 2);  // 175 x 2
    gemm_kernel<<<g2, 96>>>();

    epi_kernel<<<Nn, 64>>>(x, e, w_gate, b_gate, w_update, b_update,
                           lin_w, lin_b, out);
}

// round 9
// speedup vs baseline: 4.1464x; 3.8331x over previous
#include <cuda_runtime.h>
#include <cuda_bf16.h>
#include <cstdint>

// ---------------------------------------------------------------------------
// Problem constants
// ---------------------------------------------------------------------------
#define Nn 5570            // real nodes
#define NR 5632            // padded rows / K extent (44*128)
#define JT 576             // j columns: 560 data + 1 ones (Z) + 15 pad
#define Bb 16
#define Cc 35

// Device scratch (zero-initialized; pad regions never written -> stay 0)
__device__ __nv_bfloat16 g_Sh[(size_t)NR * NR];   // S hi   [n][m]
__device__ __nv_bfloat16 g_Sl[(size_t)NR * NR];   // S lo
__device__ __nv_bfloat16 g_Vth[(size_t)JT * NR];  // V^T hi [j][m]
__device__ __nv_bfloat16 g_Vtl[(size_t)JT * NR];  // V^T lo
__device__ float         g_X1[(size_t)NR * JT];   // S@V (unnormalized); col 560 = Z

// ---------------------------------------------------------------------------
// PTX helpers (all baseline ISA, valid on compute_103 virtual arch)
// ---------------------------------------------------------------------------
__device__ __forceinline__ uint32_t smem_u32(const void* p) {
    uint32_t a;
    asm("{ .reg .u64 t; cvta.to.shared.u64 t, %1; cvt.u32.u64 %0, t; }"
        : "=r"(a) : "l"(p));
    return a;
}
__device__ __forceinline__ void cp16(uint32_t saddr, const void* g) {
    asm volatile("cp.async.cg.shared.global [%0], [%1], 16;"
                 :: "r"(saddr), "l"(g) : "memory");
}
#define CP_COMMIT() asm volatile("cp.async.commit_group;" ::: "memory")
#define CP_WAIT1()  asm volatile("cp.async.wait_group 1;" ::: "memory")

__device__ __forceinline__ void ldsm4(uint32_t (&r)[4], uint32_t addr) {
    asm volatile("ldmatrix.sync.aligned.m8n8.x4.shared.b16 {%0,%1,%2,%3}, [%4];"
                 : "=r"(r[0]), "=r"(r[1]), "=r"(r[2]), "=r"(r[3]) : "r"(addr));
}
__device__ __forceinline__ void mma_bf16(float* c, const uint32_t* a,
                                         const uint32_t* b) {
    asm volatile(
        "mma.sync.aligned.m16n8k16.row.col.f32.bf16.bf16.f32 "
        "{%0,%1,%2,%3}, {%4,%5,%6,%7}, {%8,%9}, {%0,%1,%2,%3};"
        : "+f"(c[0]), "+f"(c[1]), "+f"(c[2]), "+f"(c[3])
        : "r"(a[0]), "r"(a[1]), "r"(a[2]), "r"(a[3]), "r"(b[0]), "r"(b[1]));
}
static __device__ __forceinline__ uint32_t swz(uint32_t off) {
    return off ^ ((off >> 3) & 0x70);   // SW128 for 128B rows
}

// Fast exp via exp2 poly (x >= 0, x <= ~60)
__device__ __forceinline__ float fast_exp(float x) {
    float t = x * 1.4426950408889634f;
    float fn = rintf(t);
    float f = t - fn;
    float p = 0.0013333558f;
    p = fmaf(p, f, 0.0096181291f);
    p = fmaf(p, f, 0.0555041087f);
    p = fmaf(p, f, 0.2402265069f);
    p = fmaf(p, f, 0.6931471806f);
    p = fmaf(p, f, 1.0f);
    return __int_as_float(__float_as_int(p) + ((int)fn << 23));
}
__device__ __forceinline__ void bf16_split(float v, __nv_bfloat16& hi,
                                           __nv_bfloat16& lo) {
    hi = __float2bfloat16(v);
    lo = __float2bfloat16(v - __bfloat162float(hi));
}

// ---------------------------------------------------------------------------
// Kernel 1: build V^T [j][m] bf16 hi/lo. Grid (44 m-tiles, 16 batches).
// ---------------------------------------------------------------------------
__global__ void prep_vt_kernel(const float* __restrict__ x) {
    __shared__ float sx[128 * Cc];
    const int m0 = blockIdx.x * 128;
    const int b  = blockIdx.y;
    const int tid = threadIdx.x;   // 256

    const int limit = min(128, Nn - m0) * Cc;
    const float* xb = x + ((size_t)b * Nn + m0) * Cc;
    for (int t = tid; t < 128 * Cc; t += 256)
        sx[t] = (t < limit) ? xb[t] : 0.0f;
    __syncthreads();

    for (int t = tid; t < Cc * 128; t += 256) {
        int c  = t >> 7;
        int mm = t & 127;
        int m  = m0 + mm;
        if (m < Nn) {
            __nv_bfloat16 hi, lo;
            bf16_split(sx[mm * Cc + c], hi, lo);
            size_t row = (size_t)(b * Cc + c) * NR + m;
            g_Vth[row] = hi;
            g_Vtl[row] = lo;
        }
    }
    if (b == 0 && tid < 128) {
        int m = m0 + tid;
        if (m < Nn) {
            g_Vth[(size_t)560 * NR + m] = __float2bfloat16(1.0f);
            g_Vtl[(size_t)560 * NR + m] = __float2bfloat16(0.0f);
        }
    }
}

// ---------------------------------------------------------------------------
// Kernel 2: S[n,m] = exp(relu(e_n . e_m)) -> bf16 hi/lo. Tile 128n x 128m.
// Pad m-cols get exp(0)=1, harmless: V^T pad rows (m >= Nn) are zero.
// ---------------------------------------------------------------------------
__global__ __launch_bounds__(256) void score_kernel(const float* __restrict__ e) {
    __shared__ float4 sem[128];
    const int n0 = blockIdx.y * 128;
    const int m0 = blockIdx.x * 128;
    const int tid = threadIdx.x;
    const int w = tid >> 5, l = tid & 31;

    if (tid < 128) {
        int m = m0 + tid;
        sem[tid] = (m < Nn) ? ((const float4*)e)[m]
                            : make_float4(0.f, 0.f, 0.f, 0.f);
    }
    __syncthreads();

    float4 em0 = sem[l * 4 + 0], em1 = sem[l * 4 + 1];
    float4 em2 = sem[l * 4 + 2], em3 = sem[l * 4 + 3];

#pragma unroll 4
    for (int rr = 0; rr < 16; ++rr) {
        int n = n0 + w * 16 + rr;
        if (n >= Nn) break;
        float4 en = ((const float4*)e)[n];   // warp-uniform -> broadcast
        float d0 = fmaf(en.x, em0.x, fmaf(en.y, em0.y, fmaf(en.z, em0.z, en.w * em0.w)));
        float d1 = fmaf(en.x, em1.x, fmaf(en.y, em1.y, fmaf(en.z, em1.z, en.w * em1.w)));
        float d2 = fmaf(en.x, em2.x, fmaf(en.y, em2.y, fmaf(en.z, em2.z, en.w * em2.w)));
        float d3 = fmaf(en.x, em3.x, fmaf(en.y, em3.y, fmaf(en.z, em3.z, en.w * em3.w)));
        float s0 = fast_exp(fmaxf(d0, 0.0f));
        float s1 = fast_exp(fmaxf(d1, 0.0f));
        float s2 = fast_exp(fmaxf(d2, 0.0f));
        float s3 = fast_exp(fmaxf(d3, 0.0f));
        __nv_bfloat16 h0, h1, h2, h3, l0, l1, l2, l3;
        bf16_split(s0, h0, l0); bf16_split(s1, h1, l1);
        bf16_split(s2, h2, l2); bf16_split(s3, h3, l3);
        size_t off = (size_t)n * NR + m0 + l * 4;
        __nv_bfloat162* oh = (__nv_bfloat162*)(g_Sh + off);
        __nv_bfloat162* ol = (__nv_bfloat162*)(g_Sl + off);
        oh[0] = __nv_bfloat162(h0, h1); oh[1] = __nv_bfloat162(h2, h3);
        ol[0] = __nv_bfloat162(l0, l1); ol[1] = __nv_bfloat162(l2, l3);
    }
}

// ---------------------------------------------------------------------------
// Kernel 3: HMMA GEMM. X1[n,j] = sum_m S[n,m] V^T[j,m], 3-pass bf16 split.
// CTA: 128(n) x 192(j), BK=64, double-buffered cp.async, ldmatrix + mma.sync.
//
// Swizzle algebra for ldmatrix addressing (the R8 bug): for 128B rows,
//   swz(row*128 + b) = row*128 + (b ^ ((row&7)<<4)),
// and since the in-row byte base (bit 4) and ks<<5 (bits 5-6) are disjoint,
//   correct addr = row*128 + ((base ^ xorv) ^ (ks<<5)),  xorv=(row&7)<<4.
// Never add ks*32 AFTER swizzling (carries out of bits 5-6 corrupt the row).
// ---------------------------------------------------------------------------
#define OFF_AH 0
#define OFF_AL 16384
#define OFF_BH 32768
#define OFF_BL 57344
#define BUF_STRIDE 81920
#define SMEM_REQ (2 * BUF_STRIDE + 1024)

__global__ __launch_bounds__(256, 1) void gemm_kernel() {
    extern __shared__ char dsm[];
    uint32_t raw = smem_u32(dsm);
    const uint32_t base = raw + ((1024u - (raw & 1023u)) & 1023u);

    const int tid = threadIdx.x;
    const int lid = tid & 31;
    const int wm = (tid >> 5) & 1;     // 2 warps along m (64 rows each)
    const int wn = tid >> 6;           // 4 warps along n (48 cols each)
    const int n0 = blockIdx.x * 128;
    const int j0 = blockIdx.y * 192;

    const char* srcAH = (const char*)g_Sh  + (size_t)n0 * (NR * 2);
    const char* srcAL = (const char*)g_Sl  + (size_t)n0 * (NR * 2);
    const char* srcBH = (const char*)g_Vth + (size_t)j0 * (NR * 2);
    const char* srcBL = (const char*)g_Vtl + (size_t)j0 * (NR * 2);

    const int lrow = tid >> 3;         // 0..31, +rr*32
    const int lq   = tid & 7;          // 16B slot in 128B row

    // ldmatrix per-lane address components (swizzle-correct per-ks form)
    uint32_t arow[4], axor[4];
#pragma unroll
    for (int mt = 0; mt < 4; ++mt) {
        int row = wm * 64 + mt * 16 + (lid & 15);
        arow[mt] = row * 128;
        axor[mt] = ((lid >> 4) * 16) ^ ((row & 7) << 4);
    }
    uint32_t brow[3], bxor[3];
#pragma unroll
    for (int bp = 0; bp < 3; ++bp) {
        int row = wn * 48 + bp * 16 + ((lid >> 4) << 3) + (lid & 7);
        brow[bp] = row * 128;
        bxor[bp] = (((lid >> 3) & 1) * 16) ^ ((row & 7) << 4);
    }

    float acc[4][6][4] = {};

    // ---- prologue: chunk 0 ----
    {
        const uint32_t soff = base;
        const size_t kb = (size_t)lq * 16;
#pragma unroll
        for (int rr = 0; rr < 4; ++rr) {
            int row = lrow + rr * 32;
            uint32_t so = swz(row * 128 + lq * 16);
            size_t g = (size_t)row * (NR * 2) + kb;
            cp16(soff + OFF_AH + so, srcAH + g);
            cp16(soff + OFF_AL + so, srcAL + g);
        }
#pragma unroll
        for (int rr = 0; rr < 6; ++rr) {
            int row = lrow + rr * 32;
            uint32_t so = swz(row * 128 + lq * 16);
            size_t g = (size_t)row * (NR * 2) + kb;
            cp16(soff + OFF_BH + so, srcBH + g);
            cp16(soff + OFF_BL + so, srcBL + g);
        }
        CP_COMMIT();
    }

    for (int it = 0; it < NR / 64; ++it) {
        const int bsel = it & 1;
        if (it + 1 < NR / 64) {
            const uint32_t soff = base + (bsel ^ 1) * BUF_STRIDE;
            const size_t kb = (size_t)(it + 1) * 128 + lq * 16;
#pragma unroll
            for (int rr = 0; rr < 4; ++rr) {
                int row = lrow + rr * 32;
                uint32_t so = swz(row * 128 + lq * 16);
                size_t g = (size_t)row * (NR * 2) + kb;
                cp16(soff + OFF_AH + so, srcAH + g);
                cp16(soff + OFF_AL + so, srcAL + g);
            }
#pragma unroll
            for (int rr = 0; rr < 6; ++rr) {
                int row = lrow + rr * 32;
                uint32_t so = swz(row * 128 + lq * 16);
                size_t g = (size_t)row * (NR * 2) + kb;
                cp16(soff + OFF_BH + so, srcBH + g);
                cp16(soff + OFF_BL + so, srcBL + g);
            }
        }
        CP_COMMIT();
        CP_WAIT1();
        __syncthreads();

        const uint32_t soff = base + bsel * BUF_STRIDE;
#pragma unroll
        for (int ks = 0; ks < 4; ++ks) {
            const uint32_t kx = (uint32_t)ks << 5;
            uint32_t Ah[4][4], Al[4][4], Bh[6][2], Bl[6][2];
#pragma unroll
            for (int mt = 0; mt < 4; ++mt) {
                uint32_t ad = soff + arow[mt] + (axor[mt] ^ kx);
                ldsm4(Ah[mt], ad + OFF_AH);
                ldsm4(Al[mt], ad + OFF_AL);
            }
#pragma unroll
            for (int bp = 0; bp < 3; ++bp) {
                uint32_t bd = soff + brow[bp] + (bxor[bp] ^ kx);
                uint32_t r[4];
                ldsm4(r, bd + OFF_BH);
                Bh[2 * bp][0] = r[0]; Bh[2 * bp][1] = r[1];
                Bh[2 * bp + 1][0] = r[2]; Bh[2 * bp + 1][1] = r[3];
                ldsm4(r, bd + OFF_BL);
                Bl[2 * bp][0] = r[0]; Bl[2 * bp][1] = r[1];
                Bl[2 * bp + 1][0] = r[2]; Bl[2 * bp + 1][1] = r[3];
            }
#pragma unroll
            for (int mt = 0; mt < 4; ++mt)
#pragma unroll
                for (int nt = 0; nt < 6; ++nt) {
                    mma_bf16(acc[mt][nt], Ah[mt], Bh[nt]);
                    mma_bf16(acc[mt][nt], Al[mt], Bh[nt]);
                    mma_bf16(acc[mt][nt], Ah[mt], Bl[nt]);
                }
        }
        __syncthreads();
    }

    // epilogue: D frag lane map: rows lid/4 and +8, cols 2*(lid%4)+{0,1}
    const int r4 = lid >> 2;
    const int c2 = (lid & 3) * 2;
#pragma unroll
    for (int mt = 0; mt < 4; ++mt) {
        int row = n0 + wm * 64 + mt * 16 + r4;
#pragma unroll
        for (int nt = 0; nt < 6; ++nt) {
            int col = j0 + wn * 48 + nt * 8 + c2;
            *(float2*)&g_X1[(size_t)row * JT + col] =
                make_float2(acc[mt][nt][0], acc[mt][nt][1]);
            *(float2*)&g_X1[(size_t)(row + 8) * JT + col] =
                make_float2(acc[mt][nt][2], acc[mt][nt][3]);
        }
    }
}

// ---------------------------------------------------------------------------
// Kernel 4: per-node epilogue (H=0 => only R and C gates matter).
// ---------------------------------------------------------------------------
__global__ void epi_kernel(const float* __restrict__ x,
                           const float* __restrict__ e,
                           const float* __restrict__ w_gate,
                           const float* __restrict__ b_gate,
                           const float* __restrict__ w_update,
                           const float* __restrict__ b_update,
                           const float* __restrict__ lin_w,
                           const float* __restrict__ lin_b,
                           float* __restrict__ out) {
    const int n = blockIdx.x;
    const int tid = threadIdx.x;  // 64

    __shared__ float se[4];
    __shared__ float sWg[2][35][4];
    __shared__ float sbg[4];
    __shared__ float sWu[2][35][2];
    __shared__ float sbu[2];
    __shared__ float sxs[16][36];
    __shared__ float sxg[16][36];
    __shared__ float sy[16][2];

    if (tid < 4) se[tid] = e[n * 4 + tid];
    __syncthreads();

    for (int t = tid; t < 280; t += 64) {
        int o = t & 3, t2 = t >> 2;
        int i = t2 % 35, k = t2 / 35;
        float s = 0.0f;
#pragma unroll
        for (int d = 0; d < 4; ++d)
            s += se[d] * w_gate[(((d * 2) + k) * 37 + i) * 4 + o];
        sWg[k][i][o] = s;
    }
    if (tid < 4) {
        float s = 0.0f;
#pragma unroll
        for (int d = 0; d < 4; ++d) s += se[d] * b_gate[d * 4 + tid];
        sbg[tid] = s;
    }
    for (int t = tid; t < 140; t += 64) {
        int o = t & 1, t2 = t >> 1;
        int i = t2 % 35, k = t2 / 35;
        float s = 0.0f;
#pragma unroll
        for (int d = 0; d < 4; ++d)
            s += se[d] * w_update[(((d * 2) + k) * 37 + i) * 2 + o];
        sWu[k][i][o] = s;
    }
    if (tid < 2) {
        float s = 0.0f;
#pragma unroll
        for (int d = 0; d < 4; ++d) s += se[d] * b_update[d * 2 + tid];
        sbu[tid] = s;
    }

    const float invZ = 1.0f / g_X1[(size_t)n * JT + 560];
    for (int t = tid; t < 560; t += 64) {
        int b = t / 35, c = t - b * 35;
        sxs[b][c] = x[((size_t)b * Nn + n) * 35 + c];
        sxg[b][c] = g_X1[(size_t)n * JT + t] * invZ;
    }
    __syncthreads();

    if (tid < 32) {
        int b = tid >> 1, o = tid & 1;
        float gr = sbg[o + 2];
        float cu = sbu[o];
#pragma unroll
        for (int i = 0; i < 35; ++i) {
            float xs = sxs[b][i];
            float xg = sxg[b][i];
            gr += xs * sWg[0][i][o + 2] + xg * sWg[1][i][o + 2];
            cu += xs * sWu[0][i][o] + xg * sWu[1][i][o];
        }
        float R = 1.0f / (1.0f + __expf(-gr));
        float Cv = tanhf(cu);
        float h = (1.0f - R) * Cv;
        sy[b][o] = fmaxf(h, 0.0f) * lin_w[o];
    }
    __syncthreads();

    if (tid < 16) out[tid * Nn + n] = sy[tid][0] + sy[tid][1] + lin_b[0];
}

// ---------------------------------------------------------------------------
extern "C" void kernel_launch(void* const* d_in, const int* in_sizes, int n_in,
                              void* d_out, int out_size) {
    const float* x        = (const float*)d_in[0];
    const float* e        = (const float*)d_in[1];
    const float* w_gate   = (const float*)d_in[2];
    const float* b_gate   = (const float*)d_in[3];
    const float* w_update = (const float*)d_in[4];
    const float* b_update = (const float*)d_in[5];
    const float* lin_w    = (const float*)d_in[6];
    const float* lin_b    = (const float*)d_in[7];
    float* out = (float*)d_out;

    (void)cudaFuncSetAttribute(gemm_kernel,
                               cudaFuncAttributeMaxDynamicSharedMemorySize,
                               SMEM_REQ);

    prep_vt_kernel<<<dim3(44, 16), 256>>>(x);
    score_kernel<<<dim3(44, 44), 256>>>(e);
    gemm_kernel<<<dim3(44, 3), 256, SMEM_REQ>>>();
    epi_kernel<<<Nn, 64>>>(x, e, w_gate, b_gate, w_update, b_update,
                           lin_w, lin_b, out);
}

// round 15
// speedup vs baseline: 7.3536x; 1.7735x over previous
#include <cuda_runtime.h>
#include <cuda_fp16.h>
#include <cstdint>

// ---------------------------------------------------------------------------
// Problem constants
// ---------------------------------------------------------------------------
#define Nn 5570            // real nodes
#define NR 5632            // padded rows / K extent (44*128)
#define JT 576             // j columns: 560 data + 1 ones (Z) + 15 pad
#define Bb 16
#define Cc 35

// Device scratch (zero-initialized; pad regions never written -> stay 0).
// g_rowmax: atomicMax is idempotent for fixed inputs -> deterministic across
// graph replays (monotone toward the same fixed point from 0).
__device__ __half    g_Sf[(size_t)NR * NR];    // S' = exp(dot - rmax + ln1024), fp16
__device__ __half    g_Vtf[(size_t)JT * NR];   // V^T [j][m], fp16
__device__ float     g_X1[(size_t)NR * JT];    // S'@V (scaled); col 560 = Z'
__device__ unsigned  g_rowmax[NR];             // float bits of rowwise max relu(dot)

// ---------------------------------------------------------------------------
// PTX helpers (baseline ISA only; valid under virtual arch compute_103)
// ---------------------------------------------------------------------------
__device__ __forceinline__ uint32_t smem_u32(const void* p) {
    uint32_t a;
    asm("{ .reg .u64 t; cvta.to.shared.u64 t, %1; cvt.u32.u64 %0, t; }"
        : "=r"(a) : "l"(p));
    return a;
}
__device__ __forceinline__ void cp16(uint32_t saddr, const void* g) {
    asm volatile("cp.async.cg.shared.global [%0], [%1], 16;"
                 :: "r"(saddr), "l"(g) : "memory");
}
#define CP_COMMIT() asm volatile("cp.async.commit_group;" ::: "memory")
#define CP_WAIT1()  asm volatile("cp.async.wait_group 1;" ::: "memory")

__device__ __forceinline__ void ldsm4(uint32_t (&r)[4], uint32_t addr) {
    asm volatile("ldmatrix.sync.aligned.m8n8.x4.shared.b16 {%0,%1,%2,%3}, [%4];"
                 : "=r"(r[0]), "=r"(r[1]), "=r"(r[2]), "=r"(r[3]) : "r"(addr));
}
__device__ __forceinline__ void mma_f16(float* c, const uint32_t* a,
                                        const uint32_t* b) {
    asm volatile(
        "mma.sync.aligned.m16n8k16.row.col.f32.f16.f16.f32 "
        "{%0,%1,%2,%3}, {%4,%5,%6,%7}, {%8,%9}, {%0,%1,%2,%3};"
        : "+f"(c[0]), "+f"(c[1]), "+f"(c[2]), "+f"(c[3])
        : "r"(a[0]), "r"(a[1]), "r"(a[2]), "r"(a[3]), "r"(b[0]), "r"(b[1]));
}
static __device__ __forceinline__ uint32_t swz(uint32_t off) {
    return off ^ ((off >> 3) & 0x70);   // SW128 for 128B rows
}

// Fast exp via exp2 poly; valid for x in [-50, 10] (result stays normal fp32)
__device__ __forceinline__ float fast_exp(float x) {
    float t = x * 1.4426950408889634f;
    float fn = rintf(t);
    float f = t - fn;
    float p = 0.0013333558f;
    p = fmaf(p, f, 0.0096181291f);
    p = fmaf(p, f, 0.0555041087f);
    p = fmaf(p, f, 0.2402265069f);
    p = fmaf(p, f, 0.6931471806f);
    p = fmaf(p, f, 1.0f);
    return __int_as_float(__float_as_int(p) + ((int)fn << 23));
}

// ---------------------------------------------------------------------------
// Kernel 1: build V^T [j][m] fp16. Grid (44 m-tiles, 16 batches).
// ---------------------------------------------------------------------------
__global__ void prep_vt_kernel(const float* __restrict__ x) {
    __shared__ float sx[128 * Cc];
    const int m0 = blockIdx.x * 128;
    const int b  = blockIdx.y;
    const int tid = threadIdx.x;   // 256

    const int limit = min(128, Nn - m0) * Cc;
    const float* xb = x + ((size_t)b * Nn + m0) * Cc;
    for (int t = tid; t < 128 * Cc; t += 256)
        sx[t] = (t < limit) ? xb[t] : 0.0f;
    __syncthreads();

    for (int t = tid; t < Cc * 128; t += 256) {
        int c  = t >> 7;
        int mm = t & 127;
        int m  = m0 + mm;
        if (m < Nn)
            g_Vtf[(size_t)(b * Cc + c) * NR + m] = __float2half(sx[mm * Cc + c]);
    }
    if (b == 0 && tid < 128) {
        int m = m0 + tid;
        if (m < Nn) g_Vtf[(size_t)560 * NR + m] = __float2half(1.0f);
    }
}

// ---------------------------------------------------------------------------
// Kernel 2: row max of relu(e_n . e_m). Grid (11 m-tiles x 44 n-tiles).
// Positive floats: uint compare == float compare, so atomicMax on bits works.
// ---------------------------------------------------------------------------
__global__ __launch_bounds__(256) void rowmax_kernel(const float* __restrict__ e) {
    __shared__ float4 sem[512];
    const int m0 = blockIdx.x * 512;
    const int n0 = blockIdx.y * 128;
    const int tid = threadIdx.x;

    for (int t = tid; t < 512; t += 256) {
        int m = m0 + t;
        sem[t] = (m < Nn) ? ((const float4*)e)[m]
                          : make_float4(0.f, 0.f, 0.f, 0.f);
    }
    __syncthreads();

    const int row = tid >> 1, half = tid & 1;
    const int n = n0 + row;
    if (n < Nn) {
        float4 en = ((const float4*)e)[n];
        float mx = 0.0f;
        const float4* sp = sem + half * 256;
#pragma unroll 8
        for (int i = 0; i < 256; ++i) {
            float4 em = sp[i];
            float d = fmaf(en.x, em.x, fmaf(en.y, em.y,
                       fmaf(en.z, em.z, en.w * em.w)));
            mx = fmaxf(mx, d);
        }
        mx = fmaxf(mx, __shfl_xor_sync(0xffffffffu, mx, 1));
        if (half == 0)
            atomicMax(&g_rowmax[n], __float_as_uint(mx));
    }
}

// ---------------------------------------------------------------------------
// Kernel 3: S'[n,m] = exp(relu(dot) - rmax + ln1024) in fp16 (max value 1024,
// no overflow; underflow cut at 6e-11 of max -> negligible). Tile 128x128.
// The exp(-rmax+ln1024) row scale cancels exactly in X1/Z at the epilogue.
// ---------------------------------------------------------------------------
__global__ __launch_bounds__(256) void score_kernel(const float* __restrict__ e) {
    __shared__ float4 sem[128];
    const int n0 = blockIdx.y * 128;
    const int m0 = blockIdx.x * 128;
    const int tid = threadIdx.x;
    const int w = tid >> 5, l = tid & 31;

    if (tid < 128) {
        int m = m0 + tid;
        sem[tid] = (m < Nn) ? ((const float4*)e)[m]
                            : make_float4(0.f, 0.f, 0.f, 0.f);
    }
    __syncthreads();

    float4 em0 = sem[l * 4 + 0], em1 = sem[l * 4 + 1];
    float4 em2 = sem[l * 4 + 2], em3 = sem[l * 4 + 3];

#pragma unroll 4
    for (int rr = 0; rr < 16; ++rr) {
        int n = n0 + w * 16 + rr;
        if (n >= Nn) break;
        float4 en = ((const float4*)e)[n];   // warp-uniform -> broadcast
        float bias = 6.931471806f - __uint_as_float(g_rowmax[n]);
        float d0 = fmaf(en.x, em0.x, fmaf(en.y, em0.y, fmaf(en.z, em0.z, en.w * em0.w)));
        float d1 = fmaf(en.x, em1.x, fmaf(en.y, em1.y, fmaf(en.z, em1.z, en.w * em1.w)));
        float d2 = fmaf(en.x, em2.x, fmaf(en.y, em2.y, fmaf(en.z, em2.z, en.w * em2.w)));
        float d3 = fmaf(en.x, em3.x, fmaf(en.y, em3.y, fmaf(en.z, em3.z, en.w * em3.w)));
        float s0 = fast_exp(fmaxf(d0, 0.0f) + bias);
        float s1 = fast_exp(fmaxf(d1, 0.0f) + bias);
        float s2 = fast_exp(fmaxf(d2, 0.0f) + bias);
        float s3 = fast_exp(fmaxf(d3, 0.0f) + bias);
        size_t off = (size_t)n * NR + m0 + l * 4;
        __half2* oh = (__half2*)(g_Sf + off);
        oh[0] = __floats2half2_rn(s0, s1);
        oh[1] = __floats2half2_rn(s2, s3);
    }
}

// ---------------------------------------------------------------------------
// Kernel 4: HMMA GEMM, single fp16 pass. X1[n,j] = sum_m S'[n,m] V^T[j,m].
// CTA: 128(n) x 192(j), BK=64, double-buffered cp.async, ldmatrix + mma.sync.
//
// Swizzle algebra for ldmatrix addressing: for 128B rows,
//   swz(row*128 + b) = row*128 + (b ^ ((row&7)<<4)),
// so the per-ks address is row*128 + ((base ^ xorv) ^ (ks<<5)) — never add
// ks*32 after swizzling (carry out of bits 5-6 corrupts the row).
// ---------------------------------------------------------------------------
#define OFF_A 0
#define OFF_B 16384
#define BUF_STRIDE 40960
#define SMEM_REQ (2 * BUF_STRIDE + 1024)

__global__ __launch_bounds__(256, 1) void gemm_kernel() {
    extern __shared__ char dsm[];
    uint32_t raw = smem_u32(dsm);
    const uint32_t base = raw + ((1024u - (raw & 1023u)) & 1023u);

    const int tid = threadIdx.x;
    const int lid = tid & 31;
    const int wm = (tid >> 5) & 1;     // 2 warps along n-rows (64 each)
    const int wn = tid >> 6;           // 4 warps along j-cols (48 each)
    const int n0 = blockIdx.x * 128;
    const int j0 = blockIdx.y * 192;

    const char* srcA = (const char*)g_Sf  + (size_t)n0 * (NR * 2);
    const char* srcB = (const char*)g_Vtf + (size_t)j0 * (NR * 2);

    const int lrow = tid >> 3;         // 0..31, +rr*32
    const int lq   = tid & 7;          // 16B slot in 128B row

    uint32_t arow[4], axor[4];
#pragma unroll
    for (int mt = 0; mt < 4; ++mt) {
        int row = wm * 64 + mt * 16 + (lid & 15);
        arow[mt] = row * 128;
        axor[mt] = ((lid >> 4) * 16) ^ ((row & 7) << 4);
    }
    uint32_t brow[3], bxor[3];
#pragma unroll
    for (int bp = 0; bp < 3; ++bp) {
        int row = wn * 48 + bp * 16 + ((lid >> 4) << 3) + (lid & 7);
        brow[bp] = row * 128;
        bxor[bp] = (((lid >> 3) & 1) * 16) ^ ((row & 7) << 4);
    }

    float acc[4][6][4] = {};

    // ---- prologue: chunk 0 ----
    {
        const uint32_t soff = base;
        const size_t kb = (size_t)lq * 16;
#pragma unroll
        for (int rr = 0; rr < 4; ++rr) {
            int row = lrow + rr * 32;
            cp16(soff + OFF_A + swz(row * 128 + lq * 16),
                 srcA + (size_t)row * (NR * 2) + kb);
        }
#pragma unroll
        for (int rr = 0; rr < 6; ++rr) {
            int row = lrow + rr * 32;
            cp16(soff + OFF_B + swz(row * 128 + lq * 16),
                 srcB + (size_t)row * (NR * 2) + kb);
        }
        CP_COMMIT();
    }

    for (int it = 0; it < NR / 64; ++it) {
        const int bsel = it & 1;
        if (it + 1 < NR / 64) {
            const uint32_t soff = base + (bsel ^ 1) * BUF_STRIDE;
            const size_t kb = (size_t)(it + 1) * 128 + lq * 16;
#pragma unroll
            for (int rr = 0; rr < 4; ++rr) {
                int row = lrow + rr * 32;
                cp16(soff + OFF_A + swz(row * 128 + lq * 16),
                     srcA + (size_t)row * (NR * 2) + kb);
            }
#pragma unroll
            for (int rr = 0; rr < 6; ++rr) {
                int row = lrow + rr * 32;
                cp16(soff + OFF_B + swz(row * 128 + lq * 16),
                     srcB + (size_t)row * (NR * 2) + kb);
            }
        }
        CP_COMMIT();
        CP_WAIT1();
        __syncthreads();

        const uint32_t soff = base + bsel * BUF_STRIDE;
#pragma unroll
        for (int ks = 0; ks < 4; ++ks) {
            const uint32_t kx = (uint32_t)ks << 5;
            uint32_t Af[4][4], Bf[6][2];
#pragma unroll
            for (int mt = 0; mt < 4; ++mt)
                ldsm4(Af[mt], soff + OFF_A + arow[mt] + (axor[mt] ^ kx));
#pragma unroll
            for (int bp = 0; bp < 3; ++bp) {
                uint32_t r[4];
                ldsm4(r, soff + OFF_B + brow[bp] + (bxor[bp] ^ kx));
                Bf[2 * bp][0] = r[0]; Bf[2 * bp][1] = r[1];
                Bf[2 * bp + 1][0] = r[2]; Bf[2 * bp + 1][1] = r[3];
            }
#pragma unroll
            for (int mt = 0; mt < 4; ++mt)
#pragma unroll
                for (int nt = 0; nt < 6; ++nt)
                    mma_f16(acc[mt][nt], Af[mt], Bf[nt]);
        }
        __syncthreads();
    }

    // epilogue: D frag lane map: rows lid/4 and +8, cols 2*(lid%4)+{0,1}
    const int r4 = lid >> 2;
    const int c2 = (lid & 3) * 2;
#pragma unroll
    for (int mt = 0; mt < 4; ++mt) {
        int row = n0 + wm * 64 + mt * 16 + r4;
#pragma unroll
        for (int nt = 0; nt < 6; ++nt) {
            int col = j0 + wn * 48 + nt * 8 + c2;
            *(float2*)&g_X1[(size_t)row * JT + col] =
                make_float2(acc[mt][nt][0], acc[mt][nt][1]);
            *(float2*)&g_X1[(size_t)(row + 8) * JT + col] =
                make_float2(acc[mt][nt][2], acc[mt][nt][3]);
        }
    }
}

// ---------------------------------------------------------------------------
// Kernel 5: per-node epilogue (H=0 => only R and C gates matter).
// xg = X1/Z: the exp(-rmax+ln1024) row scale cancels exactly here.
// ---------------------------------------------------------------------------
__global__ void epi_kernel(const float* __restrict__ x,
                           const float* __restrict__ e,
                           const float* __restrict__ w_gate,
                           const float* __restrict__ b_gate,
                           const float* __restrict__ w_update,
                           const float* __restrict__ b_update,
                           const float* __restrict__ lin_w,
                           const float* __restrict__ lin_b,
                           float* __restrict__ out) {
    const int n = blockIdx.x;
    const int tid = threadIdx.x;  // 64

    __shared__ float se[4];
    __shared__ float sWg[2][35][4];
    __shared__ float sbg[4];
    __shared__ float sWu[2][35][2];
    __shared__ float sbu[2];
    __shared__ float sxs[16][36];
    __shared__ float sxg[16][36];
    __shared__ float sy[16][2];

    if (tid < 4) se[tid] = e[n * 4 + tid];
    __syncthreads();

    for (int t = tid; t < 280; t += 64) {
        int o = t & 3, t2 = t >> 2;
        int i = t2 % 35, k = t2 / 35;
        float s = 0.0f;
#pragma unroll
        for (int d = 0; d < 4; ++d)
            s += se[d] * w_gate[(((d * 2) + k) * 37 + i) * 4 + o];
        sWg[k][i][o] = s;
    }
    if (tid < 4) {
        float s = 0.0f;
#pragma unroll
        for (int d = 0; d < 4; ++d) s += se[d] * b_gate[d * 4 + tid];
        sbg[tid] = s;
    }
    for (int t = tid; t < 140; t += 64) {
        int o = t & 1, t2 = t >> 1;
        int i = t2 % 35, k = t2 / 35;
        float s = 0.0f;
#pragma unroll
        for (int d = 0; d < 4; ++d)
            s += se[d] * w_update[(((d * 2) + k) * 37 + i) * 2 + o];
        sWu[k][i][o] = s;
    }
    if (tid < 2) {
        float s = 0.0f;
#pragma unroll
        for (int d = 0; d < 4; ++d) s += se[d] * b_update[d * 2 + tid];
        sbu[tid] = s;
    }

    const float invZ = 1.0f / g_X1[(size_t)n * JT + 560];
    for (int t = tid; t < 560; t += 64) {
        int b = t / 35, c = t - b * 35;
        sxs[b][c] = x[((size_t)b * Nn + n) * 35 + c];
        sxg[b][c] = g_X1[(size_t)n * JT + t] * invZ;
    }
    __syncthreads();

    if (tid < 32) {
        int b = tid >> 1, o = tid & 1;
        float gr = sbg[o + 2];
        float cu = sbu[o];
#pragma unroll
        for (int i = 0; i < 35; ++i) {
            float xs = sxs[b][i];
            float xg = sxg[b][i];
            gr += xs * sWg[0][i][o + 2] + xg * sWg[1][i][o + 2];
            cu += xs * sWu[0][i][o] + xg * sWu[1][i][o];
        }
        float R = 1.0f / (1.0f + __expf(-gr));
        float Cv = tanhf(cu);
        float h = (1.0f - R) * Cv;
        sy[b][o] = fmaxf(h, 0.0f) * lin_w[o];
    }
    __syncthreads();

    if (tid < 16) out[tid * Nn + n] = sy[tid][0] + sy[tid][1] + lin_b[0];
}

// ---------------------------------------------------------------------------
extern "C" void kernel_launch(void* const* d_in, const int* in_sizes, int n_in,
                              void* d_out, int out_size) {
    const float* x        = (const float*)d_in[0];
    const float* e        = (const float*)d_in[1];
    const float* w_gate   = (const float*)d_in[2];
    const float* b_gate   = (const float*)d_in[3];
    const float* w_update = (const float*)d_in[4];
    const float* b_update = (const float*)d_in[5];
    const float* lin_w    = (const float*)d_in[6];
    const float* lin_b    = (const float*)d_in[7];
    float* out = (float*)d_out;

    (void)cudaFuncSetAttribute(gemm_kernel,
                               cudaFuncAttributeMaxDynamicSharedMemorySize,
                               SMEM_REQ);

    prep_vt_kernel<<<dim3(44, 16), 256>>>(x);
    rowmax_kernel<<<dim3(11, 44), 256>>>(e);
    score_kernel<<<dim3(44, 44), 256>>>(e);
    gemm_kernel<<<dim3(44, 3), 256, SMEM_REQ>>>();
    epi_kernel<<<Nn, 64>>>(x, e, w_gate, b_gate, w_update, b_update,
                           lin_w, lin_b, out);
}